// round 9
// baseline (speedup 1.0000x reference)
#include <cuda_runtime.h>

#define TT     2048
#define HID    512
#define EMB    256
#define GATES  2048
#define KTAGS  48
#define START_TAG 45
#define END_TAG   46
#define NEGV  -100000.0f
#define NSCAN  64

// ---------------- device-global scratch ----------------
__device__ __align__(128) float g_x[TT * EMB];
__device__ __align__(128) float g_g[4][TT * GATES];   // 0,1: layer0 fwd/bwd; 2,3: layer1
__device__ __align__(128) float g_h0[TT * 1024];
__device__ __align__(128) float g_h1[TT * 1024];
__device__ __align__(128) float g_feats[TT * KTAGS];
// packed (float h | unsigned tag) per h element per timestep: [t][dir*512 + j]
__device__ __align__(128) unsigned long long g_hp[TT * 1024];

__device__ __forceinline__ float fsig(float x) {
    return __fdividef(1.0f, 1.0f + __expf(-x));
}
__device__ __forceinline__ float ftanh(float x) {
    return 2.0f * __fdividef(1.0f, 1.0f + __expf(-2.0f * x)) - 1.0f;
}
__device__ __forceinline__ void st_rel64(unsigned long long* p, unsigned long long v) {
    asm volatile("st.global.release.gpu.u64 [%0], %1;" :: "l"(p), "l"(v) : "memory");
}

__global__ void clear_k() {   // zero g_hp tags each replay (graph-replay safety)
    size_t i = (size_t)blockIdx.x * blockDim.x + threadIdx.x;
    if (i < (size_t)TT * 1024 / 2)
        ((ulonglong2*)g_hp)[i] = make_ulonglong2(0ull, 0ull);
}

__global__ void dummy_k() {}  // filler so ncu -s 5 captures the layer-0 scan

__global__ void embed_k(const int* __restrict__ tokens, const float* __restrict__ emb) {
    int t = blockIdx.x;
    int tok = tokens[t];
    const float4* src = (const float4*)(emb + (size_t)tok * EMB);
    float4* dst = (float4*)(g_x + (size_t)t * EMB);
    for (int i = threadIdx.x; i < EMB / 4; i += blockDim.x) dst[i] = src[i];
}

// ---------------- fp32 GEMM (NT): C[m,n] = sum_k A[m,k]*B[n,k] + b1[n]+b2[n] -----
__global__ __launch_bounds__(256) void gemm_k(int srcSel, const float* __restrict__ B,
    const float* __restrict__ bias1, const float* __restrict__ bias2, int slot, int K)
{
    __shared__ float As[2][8][128];
    __shared__ float Bs[2][8][128];
    const float* __restrict__ A = srcSel ? g_h0 : g_x;
    float* __restrict__ C = g_g[slot];
    const int N = GATES;
    const int tid = threadIdx.x;
    const int tx = tid & 15;
    const int ty = tid >> 4;
    const int mBase = blockIdx.y * 128;
    const int nBase = blockIdx.x * 128;
    const int ldRow = tid >> 1;
    const int ldCol = (tid & 1) * 4;
    const float* Ap = A + (size_t)(mBase + ldRow) * K + ldCol;
    const float* Bp = B + (size_t)(nBase + ldRow) * K + ldCol;

    float acc[8][8];
#pragma unroll
    for (int i = 0; i < 8; i++)
#pragma unroll
        for (int j = 0; j < 8; j++) acc[i][j] = 0.f;

    float4 av = *(const float4*)Ap;
    float4 bv = *(const float4*)Bp;
    As[0][ldCol + 0][ldRow] = av.x; As[0][ldCol + 1][ldRow] = av.y;
    As[0][ldCol + 2][ldRow] = av.z; As[0][ldCol + 3][ldRow] = av.w;
    Bs[0][ldCol + 0][ldRow] = bv.x; Bs[0][ldCol + 1][ldRow] = bv.y;
    Bs[0][ldCol + 2][ldRow] = bv.z; Bs[0][ldCol + 3][ldRow] = bv.w;
    __syncthreads();

    const int nk = K >> 3;
    for (int kt = 0; kt < nk; kt++) {
        const int cur = kt & 1;
        if (kt + 1 < nk) {
            av = *(const float4*)(Ap + (kt + 1) * 8);
            bv = *(const float4*)(Bp + (kt + 1) * 8);
        }
#pragma unroll
        for (int kk = 0; kk < 8; kk++) {
            float4 a0 = *(const float4*)&As[cur][kk][ty * 8];
            float4 a1 = *(const float4*)&As[cur][kk][ty * 8 + 4];
            float4 b0 = *(const float4*)&Bs[cur][kk][tx * 8];
            float4 b1 = *(const float4*)&Bs[cur][kk][tx * 8 + 4];
            float ar[8] = {a0.x, a0.y, a0.z, a0.w, a1.x, a1.y, a1.z, a1.w};
            float br[8] = {b0.x, b0.y, b0.z, b0.w, b1.x, b1.y, b1.z, b1.w};
#pragma unroll
            for (int i = 0; i < 8; i++)
#pragma unroll
                for (int j = 0; j < 8; j++)
                    acc[i][j] += ar[i] * br[j];
        }
        if (kt + 1 < nk) {
            const int nxt = cur ^ 1;
            As[nxt][ldCol + 0][ldRow] = av.x; As[nxt][ldCol + 1][ldRow] = av.y;
            As[nxt][ldCol + 2][ldRow] = av.z; As[nxt][ldCol + 3][ldRow] = av.w;
            Bs[nxt][ldCol + 0][ldRow] = bv.x; Bs[nxt][ldCol + 1][ldRow] = bv.y;
            Bs[nxt][ldCol + 2][ldRow] = bv.z; Bs[nxt][ldCol + 3][ldRow] = bv.w;
            __syncthreads();
        }
    }
#pragma unroll
    for (int i = 0; i < 8; i++) {
        int m = mBase + ty * 8 + i;
        float* Cp = C + (size_t)m * N + nBase + tx * 8;
#pragma unroll
        for (int j = 0; j < 8; j++) {
            int n = nBase + tx * 8 + j;
            Cp[j] = acc[i][j] + bias1[n] + bias2[n];
        }
    }
}

// ---------------- recurrent LSTM scan (persistent, 128 blocks x 256 threads) -----
// Block (dir,b) owns h[b*8..b*8+8); warp w computes h-index j=b*8+w, all 4 gates.
// Select-reduce: butterflies xor1,xor2 on 4 partials; lane picks gate lane&3;
// butterflies xor4,8,16 -> lane g holds gate-g total; adds own preact; computes
// its activation IN PARALLEL; lane0 gathers via 3 shuffles. One BAR per step.
// Sync: tagged-value handshake, hot poll (32 iters) before nanosleep backoff.
__global__ __launch_bounds__(256, 1) void scan_k(const float* __restrict__ whhf,
    const float* __restrict__ whhb, int gslot, int outSel, unsigned base)
{
    __shared__ float hs[2][512];
    float* __restrict__ hout = outSel ? g_h1 : g_h0;
    const int tid = threadIdx.x;
    const int bx = blockIdx.x;
    const int dir = bx >> 6;
    const int b = bx & (NSCAN - 1);
    const int w = tid >> 5;
    const int lane = tid & 31;
    const int j = b * 8 + w;
    const float* __restrict__ whh = dir ? whhb : whhf;
    const float* __restrict__ gp = g_g[gslot + dir];

    float wreg[4][16];
#pragma unroll
    for (int g = 0; g < 4; g++) {
        const float* wr = whh + (size_t)(g * HID + j) * HID;
#pragma unroll
        for (int k = 0; k < 16; k++) wreg[g][k] = wr[lane + 32 * k];
    }

    const int sel = lane & 3;
    float c = 0.f;
    for (int t = 0; t < TT; t++) {
        const int t_idx = dir ? (TT - 1 - t) : t;
        float gval = 0.f;
        if (lane < 4) gval = __ldg(gp + (size_t)t_idx * GATES + lane * HID + j);
        const int p = t & 1;
        {
            uint4 v = make_uint4(0u, 0u, 0u, 0u);
            if (t > 0) {
                const unsigned need = base + (unsigned)t;
                const int p_idx = dir ? (t_idx + 1) : (t_idx - 1);
                const uint4* src = (const uint4*)(g_hp + (size_t)p_idx * 1024 + dir * HID) + tid;
                v = __ldcg(src);
                int spins = 0;
                while (v.y < need || v.w < need) {
                    if (++spins > 32) __nanosleep(64);
                    v = __ldcg(src);
                }
            }
            ((float2*)hs[p])[tid] = make_float2(__uint_as_float(v.x), __uint_as_float(v.z));
        }
        __syncthreads();
        float a0 = 0.f, a1 = 0.f, a2 = 0.f, a3 = 0.f;
#pragma unroll
        for (int k = 0; k < 16; k++) {
            float h = hs[p][lane + 32 * k];
            a0 = fmaf(wreg[0][k], h, a0);
            a1 = fmaf(wreg[1][k], h, a1);
            a2 = fmaf(wreg[2][k], h, a2);
            a3 = fmaf(wreg[3][k], h, a3);
        }
        a0 += __shfl_xor_sync(0xffffffffu, a0, 1);
        a1 += __shfl_xor_sync(0xffffffffu, a1, 1);
        a2 += __shfl_xor_sync(0xffffffffu, a2, 1);
        a3 += __shfl_xor_sync(0xffffffffu, a3, 1);
        a0 += __shfl_xor_sync(0xffffffffu, a0, 2);
        a1 += __shfl_xor_sync(0xffffffffu, a1, 2);
        a2 += __shfl_xor_sync(0xffffffffu, a2, 2);
        a3 += __shfl_xor_sync(0xffffffffu, a3, 2);
        float vv = (sel == 0) ? a0 : (sel == 1) ? a1 : (sel == 2) ? a2 : a3;
        vv += __shfl_xor_sync(0xffffffffu, vv, 4);
        vv += __shfl_xor_sync(0xffffffffu, vv, 8);
        vv += __shfl_xor_sync(0xffffffffu, vv, 16);
        vv += gval;                                   // lanes 0..3 hold the real preacts
        float act = (sel == 2) ? ftanh(vv) : fsig(vv);
        const float fg = __shfl_sync(0xffffffffu, act, 1);
        const float gg = __shfl_sync(0xffffffffu, act, 2);
        const float og = __shfl_sync(0xffffffffu, act, 3);
        if (lane == 0) {
            c = fg * c + act * gg;
            float h = og * ftanh(c);
            __stcg(hout + (size_t)t_idx * 1024 + dir * HID + j, h);    // dense first
            unsigned long long pk = ((unsigned long long)(base + (unsigned)t + 1u) << 32)
                                    | (unsigned long long)__float_as_uint(h);
            st_rel64(g_hp + (size_t)t_idx * 1024 + dir * HID + j, pk); // release orders dense
        }
    }
}

// ---------------- final linear: feats[t,j] = h1[t]·lin_w[j] + lin_b[j] -----------
__global__ __launch_bounds__(512) void feats_k(const float* __restrict__ lin_w,
    const float* __restrict__ lin_b)
{
    __shared__ float hsm[1024];
    int t = blockIdx.x;
    for (int i = threadIdx.x; i < 1024; i += 512) hsm[i] = g_h1[(size_t)t * 1024 + i];
    __syncthreads();
    int w = threadIdx.x >> 5, lane = threadIdx.x & 31;
    for (int j = w; j < KTAGS; j += 16) {
        float s = 0.f;
        const float* wrow = lin_w + (size_t)j * 1024;
        for (int k = lane; k < 1024; k += 32) s += wrow[k] * hsm[k];
#pragma unroll
        for (int off = 16; off; off >>= 1) s += __shfl_xor_sync(0xffffffffu, s, off);
        if (lane == 0) g_feats[(size_t)t * KTAGS + j] = s + lin_b[j];
    }
}

// ---------------- CRF: 384 threads, j = tid>>3 (0..47), sub = tid&7 --------------
__global__ __launch_bounds__(384) void crf_k(const float* __restrict__ trans,
    const int* __restrict__ tags, const int* __restrict__ seqlen, float* __restrict__ out)
{
    __shared__ float alpha[2][KTAGS];
    __shared__ float scRed[384];
    const int tid = threadIdx.x;
    const int j = tid >> 3;
    const int sub = tid & 7;

    float tw[6];
#pragma unroll
    for (int kk = 0; kk < 6; kk++) tw[kk] = __ldg(trans + j * 48 + sub * 6 + kk);

    float sc = 0.f;
    for (int t = tid; t < TT; t += 384) {
        int cur = tags[t];
        int prev = t ? tags[t - 1] : START_TAG;
        sc += __ldg(trans + cur * 48 + prev) + g_feats[(size_t)t * KTAGS + cur];
    }
    scRed[tid] = sc;
    if (tid < KTAGS) alpha[0][tid] = (tid == START_TAG) ? 0.f : NEGV;
    __syncthreads();

    int p = 0;
    for (int t = 0; t < TT; t++) {
        float gf = __ldg(g_feats + (size_t)t * KTAGS + j);
        float a[6];
#pragma unroll
        for (int kk = 0; kk < 6; kk++) a[kk] = alpha[p][sub * 6 + kk] + tw[kk];
        float m = a[0];
#pragma unroll
        for (int kk = 1; kk < 6; kk++) m = fmaxf(m, a[kk]);
#pragma unroll
        for (int off = 1; off < 8; off <<= 1) m = fmaxf(m, __shfl_xor_sync(0xffffffffu, m, off));
        float s = 0.f;
#pragma unroll
        for (int kk = 0; kk < 6; kk++) s += __expf(a[kk] - m);
#pragma unroll
        for (int off = 1; off < 8; off <<= 1) s += __shfl_xor_sync(0xffffffffu, s, off);
        if (sub == 0) alpha[p ^ 1][j] = m + __logf(s) + gf;
        __syncthreads();
        p ^= 1;
    }

    if (tid == 0) {
        float score = 0.f;
        for (int k = 0; k < 384; k++) score += scRed[k];
        score += trans[END_TAG * 48 + tags[TT - 1]];
        float mm = -3.0e38f;
        for (int k = 0; k < KTAGS; k++) mm = fmaxf(mm, alpha[p][k] + trans[END_TAG * 48 + k]);
        float ss = 0.f;
        for (int k = 0; k < KTAGS; k++) ss += __expf(alpha[p][k] + trans[END_TAG * 48 + k] - mm);
        float logz = mm + __logf(ss);
        out[0] = (logz - score) / (float)seqlen[0];
    }
}

// ---------------- launch sequence ------------------------------------------------
// Order chosen so ncu (-s 5 -c 1) captures the layer-0 scan (launch index 5).
extern "C" void kernel_launch(void* const* d_in, const int* in_sizes, int n_in,
                              void* d_out, int out_size)
{
    (void)in_sizes; (void)n_in; (void)out_size;
    const int* tokens = (const int*)d_in[0];
    const int* tags   = (const int*)d_in[1];
    const int* seqlen = (const int*)d_in[2];
    const float* embed = (const float*)d_in[3];
    const float* w_ih_l0_f = (const float*)d_in[4];
    const float* w_hh_l0_f = (const float*)d_in[5];
    const float* b_ih_l0_f = (const float*)d_in[6];
    const float* b_hh_l0_f = (const float*)d_in[7];
    const float* w_ih_l0_b = (const float*)d_in[8];
    const float* w_hh_l0_b = (const float*)d_in[9];
    const float* b_ih_l0_b = (const float*)d_in[10];
    const float* b_hh_l0_b = (const float*)d_in[11];
    const float* w_ih_l1_f = (const float*)d_in[12];
    const float* w_hh_l1_f = (const float*)d_in[13];
    const float* b_ih_l1_f = (const float*)d_in[14];
    const float* b_hh_l1_f = (const float*)d_in[15];
    const float* w_ih_l1_b = (const float*)d_in[16];
    const float* w_hh_l1_b = (const float*)d_in[17];
    const float* b_ih_l1_b = (const float*)d_in[18];
    const float* b_hh_l1_b = (const float*)d_in[19];
    const float* lin_w = (const float*)d_in[20];
    const float* lin_b = (const float*)d_in[21];
    const float* trans = (const float*)d_in[22];
    float* out = (float*)d_out;

    clear_k<<<4096, 256>>>();                                         // 0
    embed_k<<<TT, 64>>>(tokens, embed);                               // 1
    dim3 gg(GATES / 128, TT / 128);
    gemm_k<<<gg, 256>>>(0, w_ih_l0_f, b_ih_l0_f, b_hh_l0_f, 0, EMB);  // 2
    gemm_k<<<gg, 256>>>(0, w_ih_l0_b, b_ih_l0_b, b_hh_l0_b, 1, EMB);  // 3
    dummy_k<<<1, 32>>>();                                             // 4
    scan_k<<<2 * NSCAN, 256>>>(w_hh_l0_f, w_hh_l0_b, 0, 0, 0u);       // 5 <- profiled
    gemm_k<<<gg, 256>>>(1, w_ih_l1_f, b_ih_l1_f, b_hh_l1_f, 2, 1024); // 6
    gemm_k<<<gg, 256>>>(1, w_ih_l1_b, b_ih_l1_b, b_hh_l1_b, 3, 1024); // 7
    scan_k<<<2 * NSCAN, 256>>>(w_hh_l1_f, w_hh_l1_b, 2, 1, (unsigned)TT); // 8
    feats_k<<<TT, 512>>>(lin_w, lin_b);                               // 9
    crf_k<<<1, 384>>>(trans, tags, seqlen, out);                      // 10
}

// round 13
// speedup vs baseline: 1.5324x; 1.5324x over previous
#include <cuda_runtime.h>

#define TT     2048
#define HID    512
#define EMB    256
#define GATES  2048
#define KTAGS  48
#define START_TAG 45
#define END_TAG   46
#define NEGV  -100000.0f
#define NSCAN  64

// ---------------- device-global scratch ----------------
__device__ __align__(128) float g_x[TT * EMB];
__device__ __align__(128) float g_g[4][TT * GATES];   // 0,1: layer0 fwd/bwd; 2,3: layer1
__device__ __align__(128) float g_h0[TT * 1024];
__device__ __align__(128) float g_h1[TT * 1024];
__device__ __align__(128) float g_feats[TT * KTAGS];
// packed (float h | unsigned tag) per h element per timestep: [t][dir*512 + j]
__device__ __align__(128) unsigned long long g_hp[TT * 1024];

__device__ __forceinline__ float fsig(float x) {
    return __fdividef(1.0f, 1.0f + __expf(-x));
}
__device__ __forceinline__ float ftanh(float x) {
    return 2.0f * __fdividef(1.0f, 1.0f + __expf(-2.0f * x)) - 1.0f;
}

__global__ void clear_k() {   // zero g_hp tags each replay (graph-replay safety)
    size_t i = (size_t)blockIdx.x * blockDim.x + threadIdx.x;
    if (i < (size_t)TT * 1024 / 2)
        ((ulonglong2*)g_hp)[i] = make_ulonglong2(0ull, 0ull);
}

__global__ void dummy_k() {}  // filler so ncu -s 5 captures the layer-0 scan

__global__ void embed_k(const int* __restrict__ tokens, const float* __restrict__ emb) {
    int t = blockIdx.x;
    int tok = tokens[t];
    const float4* src = (const float4*)(emb + (size_t)tok * EMB);
    float4* dst = (float4*)(g_x + (size_t)t * EMB);
    for (int i = threadIdx.x; i < EMB / 4; i += blockDim.x) dst[i] = src[i];
}

// ---------------- fp32 GEMM (NT), fwd+bwd fused via blockIdx.z -------------------
// C[m,n] = sum_k A[m,k]*B[n,k] + b1[n] + b2[n];  A = g_x (K=256) or g_h0 (K=1024)
__global__ __launch_bounds__(256) void gemm2_k(int srcSel,
    const float* __restrict__ Bf, const float* __restrict__ b1f, const float* __restrict__ b2f,
    const float* __restrict__ Bb, const float* __restrict__ b1b, const float* __restrict__ b2b,
    int slotBase, int K)
{
    __shared__ float As[2][8][128];
    __shared__ float Bs[2][8][128];
    const int z = blockIdx.z;
    const float* __restrict__ A = srcSel ? g_h0 : g_x;
    const float* __restrict__ B = z ? Bb : Bf;
    const float* __restrict__ bias1 = z ? b1b : b1f;
    const float* __restrict__ bias2 = z ? b2b : b2f;
    float* __restrict__ C = g_g[slotBase + z];
    const int N = GATES;
    const int tid = threadIdx.x;
    const int tx = tid & 15;
    const int ty = tid >> 4;
    const int mBase = blockIdx.y * 128;
    const int nBase = blockIdx.x * 128;
    const int ldRow = tid >> 1;
    const int ldCol = (tid & 1) * 4;
    const float* Ap = A + (size_t)(mBase + ldRow) * K + ldCol;
    const float* Bp = B + (size_t)(nBase + ldRow) * K + ldCol;

    float acc[8][8];
#pragma unroll
    for (int i = 0; i < 8; i++)
#pragma unroll
        for (int j = 0; j < 8; j++) acc[i][j] = 0.f;

    float4 av = *(const float4*)Ap;
    float4 bv = *(const float4*)Bp;
    As[0][ldCol + 0][ldRow] = av.x; As[0][ldCol + 1][ldRow] = av.y;
    As[0][ldCol + 2][ldRow] = av.z; As[0][ldCol + 3][ldRow] = av.w;
    Bs[0][ldCol + 0][ldRow] = bv.x; Bs[0][ldCol + 1][ldRow] = bv.y;
    Bs[0][ldCol + 2][ldRow] = bv.z; Bs[0][ldCol + 3][ldRow] = bv.w;
    __syncthreads();

    const int nk = K >> 3;
    for (int kt = 0; kt < nk; kt++) {
        const int cur = kt & 1;
        if (kt + 1 < nk) {
            av = *(const float4*)(Ap + (kt + 1) * 8);
            bv = *(const float4*)(Bp + (kt + 1) * 8);
        }
#pragma unroll
        for (int kk = 0; kk < 8; kk++) {
            float4 a0 = *(const float4*)&As[cur][kk][ty * 8];
            float4 a1 = *(const float4*)&As[cur][kk][ty * 8 + 4];
            float4 b0 = *(const float4*)&Bs[cur][kk][tx * 8];
            float4 b1 = *(const float4*)&Bs[cur][kk][tx * 8 + 4];
            float ar[8] = {a0.x, a0.y, a0.z, a0.w, a1.x, a1.y, a1.z, a1.w};
            float br[8] = {b0.x, b0.y, b0.z, b0.w, b1.x, b1.y, b1.z, b1.w};
#pragma unroll
            for (int i = 0; i < 8; i++)
#pragma unroll
                for (int j = 0; j < 8; j++)
                    acc[i][j] += ar[i] * br[j];
        }
        if (kt + 1 < nk) {
            const int nxt = cur ^ 1;
            As[nxt][ldCol + 0][ldRow] = av.x; As[nxt][ldCol + 1][ldRow] = av.y;
            As[nxt][ldCol + 2][ldRow] = av.z; As[nxt][ldCol + 3][ldRow] = av.w;
            Bs[nxt][ldCol + 0][ldRow] = bv.x; Bs[nxt][ldCol + 1][ldRow] = bv.y;
            Bs[nxt][ldCol + 2][ldRow] = bv.z; Bs[nxt][ldCol + 3][ldRow] = bv.w;
            __syncthreads();
        }
    }
#pragma unroll
    for (int i = 0; i < 8; i++) {
        int m = mBase + ty * 8 + i;
        float* Cp = C + (size_t)m * N + nBase + tx * 8;
#pragma unroll
        for (int j = 0; j < 8; j++) {
            int n = nBase + tx * 8 + j;
            Cp[j] = acc[i][j] + bias1[n] + bias2[n];
        }
    }
}

// ---------------- recurrent LSTM scan (persistent, 128 blocks x 256 threads) -----
// Block (dir,b) owns h[b*8..b*8+8); warp w computes h-index j=b*8+w, all 4 gates.
// Sync = R4 machinery verbatim: tagged-value handshake, plain __stcg packed store
// FIRST then dense store, nanosleep(32) on every poll retry. One BAR per step.
// Reduce = select-reduce: butterflies xor1,xor2 on the 4 gate partials; lane picks
// gate lane&3; butterflies xor4,8,16; lanes 0..3 add their preact and compute their
// activation IN PARALLEL; lane0 gathers f,g,o via 3 shuffles.
__global__ __launch_bounds__(256, 1) void scan_k(const float* __restrict__ whhf,
    const float* __restrict__ whhb, int gslot, int outSel, unsigned base)
{
    __shared__ float hs[2][512];
    float* __restrict__ hout = outSel ? g_h1 : g_h0;
    const int tid = threadIdx.x;
    const int bx = blockIdx.x;
    const int dir = bx >> 6;
    const int b = bx & (NSCAN - 1);
    const int w = tid >> 5;
    const int lane = tid & 31;
    const int j = b * 8 + w;
    const float* __restrict__ whh = dir ? whhb : whhf;
    const float* __restrict__ gp = g_g[gslot + dir];

    float wreg[4][16];
#pragma unroll
    for (int g = 0; g < 4; g++) {
        const float* wr = whh + (size_t)(g * HID + j) * HID;
#pragma unroll
        for (int k = 0; k < 16; k++) wreg[g][k] = wr[lane + 32 * k];
    }

    const int sel = lane & 3;
    float c = 0.f;
    for (int t = 0; t < TT; t++) {
        const int t_idx = dir ? (TT - 1 - t) : t;
        float gval = 0.f;
        if (lane < 4) gval = __ldg(gp + (size_t)t_idx * GATES + lane * HID + j);  // prefetch
        const int p = t & 1;
        {
            uint4 v = make_uint4(0u, 0u, 0u, 0u);
            if (t > 0) {
                const unsigned need = base + (unsigned)t;
                const int p_idx = dir ? (t_idx + 1) : (t_idx - 1);
                const uint4* src = (const uint4*)(g_hp + (size_t)p_idx * 1024 + dir * HID) + tid;
                v = __ldcg(src);
                while (v.y < need || v.w < need) { __nanosleep(32); v = __ldcg(src); }
            }
            ((float2*)hs[p])[tid] = make_float2(__uint_as_float(v.x), __uint_as_float(v.z));
        }
        __syncthreads();   // hs[p] ready (double buffer -> single BAR per step)
        float a0 = 0.f, a1 = 0.f, a2 = 0.f, a3 = 0.f;
#pragma unroll
        for (int k = 0; k < 16; k++) {
            float h = hs[p][lane + 32 * k];
            a0 = fmaf(wreg[0][k], h, a0);
            a1 = fmaf(wreg[1][k], h, a1);
            a2 = fmaf(wreg[2][k], h, a2);
            a3 = fmaf(wreg[3][k], h, a3);
        }
        a0 += __shfl_xor_sync(0xffffffffu, a0, 1);
        a1 += __shfl_xor_sync(0xffffffffu, a1, 1);
        a2 += __shfl_xor_sync(0xffffffffu, a2, 1);
        a3 += __shfl_xor_sync(0xffffffffu, a3, 1);
        a0 += __shfl_xor_sync(0xffffffffu, a0, 2);
        a1 += __shfl_xor_sync(0xffffffffu, a1, 2);
        a2 += __shfl_xor_sync(0xffffffffu, a2, 2);
        a3 += __shfl_xor_sync(0xffffffffu, a3, 2);
        float vv = (sel == 0) ? a0 : (sel == 1) ? a1 : (sel == 2) ? a2 : a3;
        vv += __shfl_xor_sync(0xffffffffu, vv, 4);
        vv += __shfl_xor_sync(0xffffffffu, vv, 8);
        vv += __shfl_xor_sync(0xffffffffu, vv, 16);
        vv += gval;                                   // lanes 0..3 hold the real preacts
        float act = (sel == 2) ? ftanh(vv) : fsig(vv);
        const float fg = __shfl_sync(0xffffffffu, act, 1);
        const float gg = __shfl_sync(0xffffffffu, act, 2);
        const float og = __shfl_sync(0xffffffffu, act, 3);
        if (lane == 0) {
            c = fg * c + act * gg;
            float h = og * ftanh(c);
            // packed store FIRST (peer critical path), plain stores — no ordering
            // needed: consumers read h from the packed word itself (8B atomic),
            // dense arrays are only read after a kernel boundary.
            unsigned long long pk = ((unsigned long long)(base + (unsigned)t + 1u) << 32)
                                    | (unsigned long long)__float_as_uint(h);
            __stcg(g_hp + (size_t)t_idx * 1024 + dir * HID + j, pk);
            __stcg(hout + (size_t)t_idx * 1024 + dir * HID + j, h);
        }
    }
}

// ---------------- final linear: feats[t,j] = h1[t]·lin_w[j] + lin_b[j] -----------
__global__ __launch_bounds__(512) void feats_k(const float* __restrict__ lin_w,
    const float* __restrict__ lin_b)
{
    __shared__ float hsm[1024];
    int t = blockIdx.x;
    for (int i = threadIdx.x; i < 1024; i += 512) hsm[i] = g_h1[(size_t)t * 1024 + i];
    __syncthreads();
    int w = threadIdx.x >> 5, lane = threadIdx.x & 31;
    for (int j = w; j < KTAGS; j += 16) {
        float s = 0.f;
        const float* wrow = lin_w + (size_t)j * 1024;
        for (int k = lane; k < 1024; k += 32) s += wrow[k] * hsm[k];
#pragma unroll
        for (int off = 16; off; off >>= 1) s += __shfl_xor_sync(0xffffffffu, s, off);
        if (lane == 0) g_feats[(size_t)t * KTAGS + j] = s + lin_b[j];
    }
}

// ---------------- CRF: 384 threads, j = tid>>3 (0..47), sub = tid&7 --------------
__global__ __launch_bounds__(384) void crf_k(const float* __restrict__ trans,
    const int* __restrict__ tags, const int* __restrict__ seqlen, float* __restrict__ out)
{
    __shared__ float alpha[2][KTAGS];
    __shared__ float scRed[384];
    const int tid = threadIdx.x;
    const int j = tid >> 3;
    const int sub = tid & 7;

    float tw[6];
#pragma unroll
    for (int kk = 0; kk < 6; kk++) tw[kk] = __ldg(trans + j * 48 + sub * 6 + kk);

    float sc = 0.f;
    for (int t = tid; t < TT; t += 384) {
        int cur = tags[t];
        int prev = t ? tags[t - 1] : START_TAG;
        sc += __ldg(trans + cur * 48 + prev) + g_feats[(size_t)t * KTAGS + cur];
    }
    scRed[tid] = sc;
    if (tid < KTAGS) alpha[0][tid] = (tid == START_TAG) ? 0.f : NEGV;
    __syncthreads();

    int p = 0;
    for (int t = 0; t < TT; t++) {
        float gf = __ldg(g_feats + (size_t)t * KTAGS + j);
        float a[6];
#pragma unroll
        for (int kk = 0; kk < 6; kk++) a[kk] = alpha[p][sub * 6 + kk] + tw[kk];
        float m = a[0];
#pragma unroll
        for (int kk = 1; kk < 6; kk++) m = fmaxf(m, a[kk]);
#pragma unroll
        for (int off = 1; off < 8; off <<= 1) m = fmaxf(m, __shfl_xor_sync(0xffffffffu, m, off));
        float s = 0.f;
#pragma unroll
        for (int kk = 0; kk < 6; kk++) s += __expf(a[kk] - m);
#pragma unroll
        for (int off = 1; off < 8; off <<= 1) s += __shfl_xor_sync(0xffffffffu, s, off);
        if (sub == 0) alpha[p ^ 1][j] = m + __logf(s) + gf;
        __syncthreads();
        p ^= 1;
    }

    if (tid == 0) {
        float score = 0.f;
        for (int k = 0; k < 384; k++) score += scRed[k];
        score += trans[END_TAG * 48 + tags[TT - 1]];
        float mm = -3.0e38f;
        for (int k = 0; k < KTAGS; k++) mm = fmaxf(mm, alpha[p][k] + trans[END_TAG * 48 + k]);
        float ss = 0.f;
        for (int k = 0; k < KTAGS; k++) ss += __expf(alpha[p][k] + trans[END_TAG * 48 + k] - mm);
        float logz = mm + __logf(ss);
        out[0] = (logz - score) / (float)seqlen[0];
    }
}

// ---------------- launch sequence ------------------------------------------------
// Order chosen so ncu (-s 5 -c 1) captures the layer-0 scan (launch index 5).
extern "C" void kernel_launch(void* const* d_in, const int* in_sizes, int n_in,
                              void* d_out, int out_size)
{
    (void)in_sizes; (void)n_in; (void)out_size;
    const int* tokens = (const int*)d_in[0];
    const int* tags   = (const int*)d_in[1];
    const int* seqlen = (const int*)d_in[2];
    const float* embed = (const float*)d_in[3];
    const float* w_ih_l0_f = (const float*)d_in[4];
    const float* w_hh_l0_f = (const float*)d_in[5];
    const float* b_ih_l0_f = (const float*)d_in[6];
    const float* b_hh_l0_f = (const float*)d_in[7];
    const float* w_ih_l0_b = (const float*)d_in[8];
    const float* w_hh_l0_b = (const float*)d_in[9];
    const float* b_ih_l0_b = (const float*)d_in[10];
    const float* b_hh_l0_b = (const float*)d_in[11];
    const float* w_ih_l1_f = (const float*)d_in[12];
    const float* w_hh_l1_f = (const float*)d_in[13];
    const float* b_ih_l1_f = (const float*)d_in[14];
    const float* b_hh_l1_f = (const float*)d_in[15];
    const float* w_ih_l1_b = (const float*)d_in[16];
    const float* w_hh_l1_b = (const float*)d_in[17];
    const float* b_ih_l1_b = (const float*)d_in[18];
    const float* b_hh_l1_b = (const float*)d_in[19];
    const float* lin_w = (const float*)d_in[20];
    const float* lin_b = (const float*)d_in[21];
    const float* trans = (const float*)d_in[22];
    float* out = (float*)d_out;

    dim3 gg(GATES / 128, TT / 128, 2);
    clear_k<<<4096, 256>>>();                                         // 0
    embed_k<<<TT, 64>>>(tokens, embed);                               // 1
    gemm2_k<<<gg, 256>>>(0, w_ih_l0_f, b_ih_l0_f, b_hh_l0_f,
                            w_ih_l0_b, b_ih_l0_b, b_hh_l0_b, 0, EMB); // 2
    dummy_k<<<1, 32>>>();                                             // 3
    dummy_k<<<1, 32>>>();                                             // 4
    scan_k<<<2 * NSCAN, 256>>>(w_hh_l0_f, w_hh_l0_b, 0, 0, 0u);       // 5 <- profiled
    gemm2_k<<<gg, 256>>>(1, w_ih_l1_f, b_ih_l1_f, b_hh_l1_f,
                            w_ih_l1_b, b_ih_l1_b, b_hh_l1_b, 2, 1024);// 6
    scan_k<<<2 * NSCAN, 256>>>(w_hh_l1_f, w_hh_l1_b, 2, 1, (unsigned)TT); // 7
    feats_k<<<TT, 512>>>(lin_w, lin_b);                               // 8
    crf_k<<<1, 384>>>(trans, tags, seqlen, out);                      // 9
}